// round 14
// baseline (speedup 1.0000x reference)
#include <cuda_runtime.h>

#define BATCH   4096
#define IN_W    1024
#define DEPTH   8
#define BLOCKS  64
#define NACT    8
#define GROW    512
#define TOTAL   5120
#define OUT_W   512

// 84 MB scratch state (static __device__ global: allowed, no runtime alloc)
__device__ float g_data[(size_t)TOTAL * BATCH];

typedef unsigned long long ull;

// Liveness masks: alive_sc[m][i] = row idx[m][i] is read by a later module;
// alive_act[m][u] = act row IN_W+512m+u is read by a later module. (m = 0..6)
__device__ unsigned char g_alive_sc[DEPTH - 1][1024];
__device__ unsigned char g_alive_act[DEPTH - 1][512];
// Prefetch masks: pref[m][i] = row idx[m][i] is NOT written by module m-1,
// so it may be gathered BEFORE cudaGridDependencySynchronize(). (m = 1..7)
__device__ unsigned char g_pref[DEPTH][1024];

__device__ __forceinline__ ull pk2(float x, float y) {
    ull r; asm("mov.b64 %0, {%1, %2};" : "=l"(r) : "f"(x), "f"(y)); return r;
}
__device__ __forceinline__ void upk2(ull v, float& x, float& y) {
    asm("mov.b64 {%0, %1}, %2;" : "=f"(x), "=f"(y) : "l"(v));
}
// Packed f32x2 FMA/MUL — Blackwell FFMA2 path (PTX-only)
__device__ __forceinline__ ull fma2(ull a, ull b, ull c) {
    ull d; asm("fma.rn.f32x2 %0, %1, %2, %3;" : "=l"(d) : "l"(a), "l"(b), "l"(c)); return d;
}
__device__ __forceinline__ ull mul2(ull a, ull b) {
    ull d; asm("mul.rn.f32x2 %0, %1, %2;" : "=l"(d) : "l"(a), "l"(b)); return d;
}
__device__ __forceinline__ float sqrt_ap(float x) {
    float r; asm("sqrt.approx.f32 %0, %1;" : "=f"(r) : "f"(x)); return r;
}
__device__ __forceinline__ float actf(float p) {
    return 0.5f * (p + sqrt_ap(fmaf(p, p, 1.0f)));
}
__device__ __forceinline__ ull mk_keep() {     // evict_last: row re-read later
    ull pol;
    asm("createpolicy.fractional.L2::evict_last.b64 %0, 1.0;" : "=l"(pol));
    return pol;
}
__device__ __forceinline__ ull mk_stream() {   // evict_first: last use
    ull pol;
    asm("createpolicy.fractional.L2::evict_first.b64 %0, 1.0;" : "=l"(pol));
    return pol;
}
__device__ __forceinline__ ull ldg_pol(const float* p, ull pol) {
    ull v;
    asm volatile("ld.global.L2::cache_hint.b64 %0, [%1], %2;"
                 : "=l"(v) : "l"(p), "l"(pol));
    return v;
}
__device__ __forceinline__ void stg_pol(float* p, ull v, ull pol) {
    asm volatile("st.global.L2::cache_hint.b64 [%0], %1, %2;"
                 :: "l"(p), "l"(v), "l"(pol));
}
__device__ __forceinline__ void stg_cs(float* p, ull v) {
    asm volatile("st.global.cs.b64 [%0], %1;" :: "l"(p), "l"(v));
}

// ---------------------------------------------------------------------------
// One-time: liveness masks (reverse sweep) + prefetch masks (forward sweep).
// ---------------------------------------------------------------------------
__global__ void alive_kernel(const int* __restrict__ indices) {
    __shared__ unsigned char mark[TOTAL];
    const int t = threadIdx.x;
    #pragma unroll
    for (int i = t; i < TOTAL; i += 1024) mark[i] = 0;
    __syncthreads();
    mark[indices[7 * 1024 + t]] = 1;          // reads of the last module
    __syncthreads();
    for (int m = DEPTH - 2; m >= 0; m--) {
        g_alive_sc[m][t] = mark[indices[m * 1024 + t]];
        if (t < 512) g_alive_act[m][t] = mark[IN_W + GROW * m + t];
        __syncthreads();
        if (m > 0) {
            mark[indices[m * 1024 + t]] = 1;
            __syncthreads();
        }
    }
    __syncthreads();
    // Forward: pref[m][i] = idx[m][i] not written by module m-1.
    for (int m = 1; m < DEPTH; m++) {
        #pragma unroll
        for (int i = t; i < TOTAL; i += 1024) mark[i] = 0;
        __syncthreads();
        if (g_alive_sc[m - 1][t]) mark[indices[(m - 1) * 1024 + t]] = 1;
        if (t < 512 && g_alive_act[m - 1][t]) mark[IN_W + GROW * (m - 1) + t] = 1;
        __syncthreads();
        g_pref[m][t] = !mark[indices[m * 1024 + t]];
        __syncthreads();
    }
}

// ---------------------------------------------------------------------------
// One butterfly module. CUDA block = (butterfly blk) x (256 batch cols).
// Thread owns 2 batch columns of all 16 rows as f32x2; transform in registers.
// occ-7 cap (72 regs) -> all 1024 CTAs resident in ONE wave, 28 warps/SM.
// PDL prologue: trig + tables + PREFETCH of rows not written by the previous
// module (their data is final: PDL chain guarantees modules <= m-2 completed).
// MODE: 0 = middle, 1 = first (input*scales), 2 = last (act -> d_out)
// ---------------------------------------------------------------------------
template<int MODE>
__global__ __launch_bounds__(128, 7)
void module_kernel(const float* __restrict__ biases,  // [512]    this module
                   const int*   __restrict__ idx,     // [1024]   this module
                   const float* __restrict__ angles,  // [8][512] this module
                   int mod,
                   const float* __restrict__ input,   // (1024,4096) for FIRST
                   const float* __restrict__ scales,  // (1024,)     for FIRST
                   float* __restrict__ out_ext)       // d_out for LAST
{
    const int blk = blockIdx.y;
    const int tid = threadIdx.x;

    __shared__ int   s_idx[16];
    __shared__ ull   s_scl[16];
    __shared__ float s_bias[NACT];
    __shared__ unsigned char s_alsc[16];
    __shared__ unsigned char s_alact[NACT];
    __shared__ unsigned char s_pref[16];
    __shared__ __align__(16) ulonglong2 s_cs[64];

    // ---- PDL prologue: tables + trig, no g_data yet ----
    if (tid < 64) {
        int L = tid >> 3, a = tid & 7;
        float sn, cs;
        sincosf(angles[L * 512 + blk * 8 + a], &sn, &cs);
        s_cs[tid] = make_ulonglong2(pk2(cs, cs), pk2(sn, sn));
    }
    if (tid < 16) {
        int row = idx[blk * 16 + tid];
        s_idx[tid]  = row;
        s_alsc[tid] = (MODE == 2) ? 0 : g_alive_sc[mod][blk * 16 + tid];
        s_pref[tid] = (MODE == 1) ? 1 : g_pref[mod][blk * 16 + tid];
        if (MODE == 1) { float s = scales[row]; s_scl[tid] = pk2(s, s); }
    }
    if (tid < 8) {
        s_bias[tid]  = biases[blk * 8 + tid];
        s_alact[tid] = (MODE == 2) ? 1 : g_alive_act[mod][blk * NACT + tid];
    }
    __syncthreads();

    const int b = (blockIdx.x * 128 + tid) * 2;   // first of 2 batch cols
    const ull SGN = 0x8000000080000000ULL;
    const ull pk  = mk_keep();
    const ull ps  = mk_stream();

    ull v[16];

    // ---- Prefetch rows NOT written by the previous module (safe pre-sync:
    //      their last writer is a module <= mod-2, already fully complete) ----
    #pragma unroll
    for (int j = 0; j < 16; j++) {
        if (s_pref[j]) {
            if (MODE == 1)
                v[j] = *(const ull*)(input + (size_t)s_idx[j] * BATCH + b);
            else
                v[j] = ldg_pol(g_data + (size_t)s_idx[j] * BATCH + b,
                               s_alsc[j] ? pk : ps);
        }
    }

    // ---- wait for previous module's stores, then fetch its rows ----
    if (MODE != 1) {
        cudaGridDependencySynchronize();
        #pragma unroll
        for (int j = 0; j < 16; j++)
            if (!s_pref[j])
                v[j] = ldg_pol(g_data + (size_t)s_idx[j] * BATCH + b,
                               s_alsc[j] ? pk : ps);
    } else {
        #pragma unroll
        for (int j = 0; j < 16; j++) v[j] = mul2(v[j], s_scl[j]);
    }

    // 4 IN rotation layers (strides 1,2,4,8), all in registers
    #pragma unroll
    for (int k = 0; k < 4; k++) {
        const int st = 1 << k;
        #pragma unroll
        for (int g = 0; g < 16; g += 2 * st) {
            #pragma unroll
            for (int j = 0; j < st; j++) {
                const int lo = g + j, hi = lo + st;
                const ulonglong2 cs = s_cs[k * 8 + (g >> 1) + j];  // LDS.128
                const ull ns = cs.y ^ SGN;                         // -s on ALU
                ull xl = v[lo], xh = v[hi];
                v[lo] = fma2(cs.x, xl, mul2(cs.y, xh));
                v[hi] = fma2(ns,   xl, mul2(cs.x, xh));
            }
        }
    }

    // Activation on rows 0..7; write live act rows (d_out for last module)
    #pragma unroll
    for (int u = 0; u < NACT; u++) {
        const float bb = s_bias[u];
        float x0, x1;
        upk2(v[u], x0, x1);
        x0 = actf(x0 + bb); x1 = actf(x1 + bb);
        v[u] = pk2(x0, x1);
        if (MODE == 2)
            stg_cs(out_ext + (size_t)(blk * NACT + u) * BATCH + b, v[u]);
        else if (s_alact[u])
            stg_pol(g_data + (size_t)(IN_W + GROW * mod + blk * NACT + u) * BATCH + b,
                    v[u], pk);
    }

    if (MODE != 2) {
        // 4 OUT rotation layers (trig layers 4..7, strides 1,2,4,8)
        #pragma unroll
        for (int k = 0; k < 4; k++) {
            const int st = 1 << k;
            #pragma unroll
            for (int g = 0; g < 16; g += 2 * st) {
                #pragma unroll
                for (int j = 0; j < st; j++) {
                    const int lo = g + j, hi = lo + st;
                    const ulonglong2 cs = s_cs[(4 + k) * 8 + (g >> 1) + j];
                    const ull ns = cs.y ^ SGN;
                    ull xl = v[lo], xh = v[hi];
                    v[lo] = fma2(cs.x, xl, mul2(cs.y, xh));
                    v[hi] = fma2(ns,   xl, mul2(cs.x, xh));
                }
            }
        }
        // Scatter back only live rows (warp-uniform predicate)
        #pragma unroll
        for (int j = 0; j < 16; j++)
            if (s_alsc[j])
                stg_pol(g_data + (size_t)s_idx[j] * BATCH + b, v[j], pk);
    }

    // Let the next PDL kernel in as soon as our work is done.
    cudaTriggerProgrammaticLaunchCompletion();
}

// ---------------------------------------------------------------------------
extern "C" void kernel_launch(void* const* d_in, const int* in_sizes, int n_in,
                              void* d_out, int out_size) {
    const float* input   = (const float*)d_in[0];   // (1024, 4096)
    const float* scales  = (const float*)d_in[1];   // (1024,)
    const float* angles  = (const float*)d_in[2];   // (8, 8, 512)
    const float* biases  = (const float*)d_in[3];   // (8, 512)
    const int*   indices = (const int*)d_in[4];     // (8, 1024)
    float* out = (float*)d_out;                     // (512, 4096)

    alive_kernel<<<1, 1024>>>(indices);

    dim3 grid(BATCH / (128 * 2), BLOCKS);   // (16, 64) = 1024 CTAs, one wave

    // Module 0: normal launch (waits on alive prep via stream order).
    module_kernel<1><<<grid, 128>>>(biases, indices, angles, 0,
                                    input, scales, nullptr);

    // Modules 1..7: PDL — overlap launch/prologue/prefetch with the previous
    // module's tail.
    for (int m = 1; m < DEPTH; m++) {
        const float* bia = biases + (size_t)m * 512;
        const int*   ix  = indices + (size_t)m * 1024;
        const float* ang = angles + (size_t)m * 4096;

        cudaLaunchConfig_t cfg = {};
        cfg.gridDim  = grid;
        cfg.blockDim = dim3(128, 1, 1);
        cfg.dynamicSmemBytes = 0;
        cfg.stream = 0;
        cudaLaunchAttribute at[1];
        at[0].id = cudaLaunchAttributeProgrammaticStreamSerialization;
        at[0].val.programmaticStreamSerializationAllowed = 1;
        cfg.attrs = at;
        cfg.numAttrs = 1;

        if (m < DEPTH - 1)
            cudaLaunchKernelEx(&cfg, module_kernel<0>, bia, ix, ang, m,
                               (const float*)nullptr, (const float*)nullptr,
                               (float*)nullptr);
        else
            cudaLaunchKernelEx(&cfg, module_kernel<2>, bia, ix, ang, m,
                               (const float*)nullptr, (const float*)nullptr,
                               out);
    }
}

// round 15
// speedup vs baseline: 1.1506x; 1.1506x over previous
#include <cuda_runtime.h>

#define BATCH   4096
#define IN_W    1024
#define DEPTH   8
#define BLOCKS  64
#define NACT    8
#define GROW    512
#define TOTAL   5120
#define OUT_W   512

// 84 MB scratch state (static __device__ global: allowed, no runtime alloc)
__device__ float g_data[(size_t)TOTAL * BATCH];

typedef unsigned long long ull;

// Liveness masks: alive_sc[m][i] = row idx[m][i] is read by a later module;
// alive_act[m][u] = act row IN_W+512m+u is read by a later module. (m = 0..6)
__device__ unsigned char g_alive_sc[DEPTH - 1][1024];
__device__ unsigned char g_alive_act[DEPTH - 1][512];

__device__ __forceinline__ ull pk2(float x, float y) {
    ull r; asm("mov.b64 %0, {%1, %2};" : "=l"(r) : "f"(x), "f"(y)); return r;
}
__device__ __forceinline__ void upk2(ull v, float& x, float& y) {
    asm("mov.b64 {%0, %1}, %2;" : "=f"(x), "=f"(y) : "l"(v));
}
// Packed f32x2 FMA/MUL — Blackwell FFMA2 path (PTX-only)
__device__ __forceinline__ ull fma2(ull a, ull b, ull c) {
    ull d; asm("fma.rn.f32x2 %0, %1, %2, %3;" : "=l"(d) : "l"(a), "l"(b), "l"(c)); return d;
}
__device__ __forceinline__ ull mul2(ull a, ull b) {
    ull d; asm("mul.rn.f32x2 %0, %1, %2;" : "=l"(d) : "l"(a), "l"(b)); return d;
}
__device__ __forceinline__ float sqrt_ap(float x) {
    float r; asm("sqrt.approx.f32 %0, %1;" : "=f"(r) : "f"(x)); return r;
}
__device__ __forceinline__ float actf(float p) {
    return 0.5f * (p + sqrt_ap(fmaf(p, p, 1.0f)));
}
__device__ __forceinline__ ull mk_keep() {     // evict_last for all state
    ull pol;
    asm("createpolicy.fractional.L2::evict_last.b64 %0, 1.0;" : "=l"(pol));
    return pol;
}
__device__ __forceinline__ ull ldg_pol(const float* p, ull pol) {
    ull v;
    asm volatile("ld.global.L2::cache_hint.b64 %0, [%1], %2;"
                 : "=l"(v) : "l"(p), "l"(pol));
    return v;
}
__device__ __forceinline__ void stg_pol(float* p, ull v, ull pol) {
    asm volatile("st.global.L2::cache_hint.b64 [%0], %1, %2;"
                 :: "l"(p), "l"(v), "l"(pol));
}
__device__ __forceinline__ void stg_cs(float* p, ull v) {
    asm volatile("st.global.cs.b64 [%0], %1;" :: "l"(p), "l"(v));
}

// ---------------------------------------------------------------------------
// One-time: liveness masks via reverse sweep over indices.
// mark[r]=1 iff row r is read by a module > m.
// ---------------------------------------------------------------------------
__global__ void alive_kernel(const int* __restrict__ indices) {
    __shared__ unsigned char mark[TOTAL];
    const int t = threadIdx.x;
    #pragma unroll
    for (int i = t; i < TOTAL; i += 1024) mark[i] = 0;
    __syncthreads();
    mark[indices[7 * 1024 + t]] = 1;          // reads of the last module
    __syncthreads();
    for (int m = DEPTH - 2; m >= 0; m--) {
        g_alive_sc[m][t] = mark[indices[m * 1024 + t]];
        if (t < 512) g_alive_act[m][t] = mark[IN_W + GROW * m + t];
        __syncthreads();
        if (m > 0) {
            mark[indices[m * 1024 + t]] = 1;
            __syncthreads();
        }
    }
}

// ---------------------------------------------------------------------------
// One butterfly module. CUDA block = (butterfly blk) x (256 batch cols).
// Thread owns 2 batch columns of all 16 rows as f32x2; transform in registers.
// occ-8 cap (64 regs) -> 32 warps/SM, 1184 slots: 1024 CTAs in ONE wave.
// PDL prologue computes trig via sincosf (overlapped with previous module's
// tail); g_data touched only after griddepsync.
// MODE: 0 = middle, 1 = first (input*scales), 2 = last (act -> d_out)
// ---------------------------------------------------------------------------
template<int MODE>
__global__ __launch_bounds__(128, 8)
void module_kernel(const float* __restrict__ biases,  // [512]    this module
                   const int*   __restrict__ idx,     // [1024]   this module
                   const float* __restrict__ angles,  // [8][512] this module
                   int mod,
                   const float* __restrict__ input,   // (1024,4096) for FIRST
                   const float* __restrict__ scales,  // (1024,)     for FIRST
                   float* __restrict__ out_ext)       // d_out for LAST
{
    const int blk = blockIdx.y;
    const int tid = threadIdx.x;

    __shared__ int   s_idx[16];
    __shared__ ull   s_scl[16];
    __shared__ float s_bias[NACT];
    __shared__ unsigned char s_alsc[16];
    __shared__ unsigned char s_alact[NACT];
    __shared__ __align__(16) ulonglong2 s_cs[64];

    // ---- PDL prologue: tables + trig only, no g_data ----
    if (tid < 64) {
        int L = tid >> 3, a = tid & 7;
        float sn, cs;
        sincosf(angles[L * 512 + blk * 8 + a], &sn, &cs);
        s_cs[tid] = make_ulonglong2(pk2(cs, cs), pk2(sn, sn));
    }
    if (tid < 16) {
        int row = idx[blk * 16 + tid];
        s_idx[tid]  = row;
        s_alsc[tid] = (MODE == 2) ? 0 : g_alive_sc[mod][blk * 16 + tid];
        if (MODE == 1) { float s = scales[row]; s_scl[tid] = pk2(s, s); }
    }
    if (tid < 8) {
        s_bias[tid]  = biases[blk * 8 + tid];
        s_alact[tid] = (MODE == 2) ? 1 : g_alive_act[mod][blk * NACT + tid];
    }
    __syncthreads();

    const int b = (blockIdx.x * 128 + tid) * 2;   // first of 2 batch cols
    const ull SGN = 0x8000000080000000ULL;
    const ull pk  = mk_keep();

    // ---- wait for previous module's stores ----
    if (MODE != 1) cudaGridDependencySynchronize();

    // Gather 16 rows (16 independent LDG.64 -> MLP=16)
    ull v[16];
    #pragma unroll
    for (int j = 0; j < 16; j++) {
        if (MODE == 1)
            v[j] = *(const ull*)(input + (size_t)s_idx[j] * BATCH + b);
        else
            v[j] = ldg_pol(g_data + (size_t)s_idx[j] * BATCH + b, pk);
    }
    if (MODE == 1) {
        #pragma unroll
        for (int j = 0; j < 16; j++) v[j] = mul2(v[j], s_scl[j]);
    }

    // 4 IN rotation layers (strides 1,2,4,8), all in registers
    #pragma unroll
    for (int k = 0; k < 4; k++) {
        const int st = 1 << k;
        #pragma unroll
        for (int g = 0; g < 16; g += 2 * st) {
            #pragma unroll
            for (int j = 0; j < st; j++) {
                const int lo = g + j, hi = lo + st;
                const ulonglong2 cs = s_cs[k * 8 + (g >> 1) + j];  // LDS.128
                const ull ns = cs.y ^ SGN;                         // -s on ALU
                ull xl = v[lo], xh = v[hi];
                v[lo] = fma2(cs.x, xl, mul2(cs.y, xh));
                v[hi] = fma2(ns,   xl, mul2(cs.x, xh));
            }
        }
    }

    // Activation on rows 0..7; write live act rows (d_out for last module)
    #pragma unroll
    for (int u = 0; u < NACT; u++) {
        const float bb = s_bias[u];
        float x0, x1;
        upk2(v[u], x0, x1);
        x0 = actf(x0 + bb); x1 = actf(x1 + bb);
        v[u] = pk2(x0, x1);
        if (MODE == 2)
            stg_cs(out_ext + (size_t)(blk * NACT + u) * BATCH + b, v[u]);
        else if (s_alact[u])
            stg_pol(g_data + (size_t)(IN_W + GROW * mod + blk * NACT + u) * BATCH + b,
                    v[u], pk);
    }

    if (MODE != 2) {
        // 4 OUT rotation layers (trig layers 4..7, strides 1,2,4,8)
        #pragma unroll
        for (int k = 0; k < 4; k++) {
            const int st = 1 << k;
            #pragma unroll
            for (int g = 0; g < 16; g += 2 * st) {
                #pragma unroll
                for (int j = 0; j < st; j++) {
                    const int lo = g + j, hi = lo + st;
                    const ulonglong2 cs = s_cs[(4 + k) * 8 + (g >> 1) + j];
                    const ull ns = cs.y ^ SGN;
                    ull xl = v[lo], xh = v[hi];
                    v[lo] = fma2(cs.x, xl, mul2(cs.y, xh));
                    v[hi] = fma2(ns,   xl, mul2(cs.x, xh));
                }
            }
        }
        // Scatter back only live rows (warp-uniform predicate)
        #pragma unroll
        for (int j = 0; j < 16; j++)
            if (s_alsc[j])
                stg_pol(g_data + (size_t)s_idx[j] * BATCH + b, v[j], pk);
    }

    // Let the next PDL kernel in as soon as our work is done.
    cudaTriggerProgrammaticLaunchCompletion();
}

// ---------------------------------------------------------------------------
extern "C" void kernel_launch(void* const* d_in, const int* in_sizes, int n_in,
                              void* d_out, int out_size) {
    const float* input   = (const float*)d_in[0];   // (1024, 4096)
    const float* scales  = (const float*)d_in[1];   // (1024,)
    const float* angles  = (const float*)d_in[2];   // (8, 8, 512)
    const float* biases  = (const float*)d_in[3];   // (8, 512)
    const int*   indices = (const int*)d_in[4];     // (8, 1024)
    float* out = (float*)d_out;                     // (512, 4096)

    alive_kernel<<<1, 1024>>>(indices);

    dim3 grid(BATCH / (128 * 2), BLOCKS);   // (16, 64) = 1024 CTAs, one wave

    // Module 0: normal launch (waits on alive prep via stream order).
    module_kernel<1><<<grid, 128>>>(biases, indices, angles, 0,
                                    input, scales, nullptr);

    // Modules 1..7: PDL — overlap launch/prologue (incl. sincos) with the
    // previous module's tail.
    for (int m = 1; m < DEPTH; m++) {
        const float* bia = biases + (size_t)m * 512;
        const int*   ix  = indices + (size_t)m * 1024;
        const float* ang = angles + (size_t)m * 4096;

        cudaLaunchConfig_t cfg = {};
        cfg.gridDim  = grid;
        cfg.blockDim = dim3(128, 1, 1);
        cfg.dynamicSmemBytes = 0;
        cfg.stream = 0;
        cudaLaunchAttribute at[1];
        at[0].id = cudaLaunchAttributeProgrammaticStreamSerialization;
        at[0].val.programmaticStreamSerializationAllowed = 1;
        cfg.attrs = at;
        cfg.numAttrs = 1;

        if (m < DEPTH - 1)
            cudaLaunchKernelEx(&cfg, module_kernel<0>, bia, ix, ang, m,
                               (const float*)nullptr, (const float*)nullptr,
                               (float*)nullptr);
        else
            cudaLaunchKernelEx(&cfg, module_kernel<2>, bia, ix, ang, m,
                               (const float*)nullptr, (const float*)nullptr,
                               out);
    }
}

// round 16
// speedup vs baseline: 1.1883x; 1.0328x over previous
#include <cuda_runtime.h>

#define BATCH   4096
#define IN_W    1024
#define DEPTH   8
#define BLOCKS  64
#define NACT    8
#define GROW    512
#define TOTAL   5120
#define OUT_W   512

// 84 MB scratch state (static __device__ global: allowed, no runtime alloc)
__device__ float g_data[(size_t)TOTAL * BATCH];

typedef unsigned long long ull;

// Liveness masks: alive_sc[m][i] = row idx[m][i] is read by a later module;
// alive_act[m][u] = act row IN_W+512m+u is read by a later module. (m = 0..6)
__device__ unsigned char g_alive_sc[DEPTH - 1][1024];
__device__ unsigned char g_alive_act[DEPTH - 1][512];

__device__ __forceinline__ ull pk2(float x, float y) {
    ull r; asm("mov.b64 %0, {%1, %2};" : "=l"(r) : "f"(x), "f"(y)); return r;
}
__device__ __forceinline__ void upk2(ull v, float& x, float& y) {
    asm("mov.b64 {%0, %1}, %2;" : "=f"(x), "=f"(y) : "l"(v));
}
// Packed f32x2 FMA/MUL — Blackwell FFMA2 path (PTX-only)
__device__ __forceinline__ ull fma2(ull a, ull b, ull c) {
    ull d; asm("fma.rn.f32x2 %0, %1, %2, %3;" : "=l"(d) : "l"(a), "l"(b), "l"(c)); return d;
}
__device__ __forceinline__ ull mul2(ull a, ull b) {
    ull d; asm("mul.rn.f32x2 %0, %1, %2;" : "=l"(d) : "l"(a), "l"(b)); return d;
}
__device__ __forceinline__ float sqrt_ap(float x) {
    float r; asm("sqrt.approx.f32 %0, %1;" : "=f"(r) : "f"(x)); return r;
}
__device__ __forceinline__ float actf(float p) {
    return 0.5f * (p + sqrt_ap(fmaf(p, p, 1.0f)));
}
__device__ __forceinline__ ull mk_keep() {     // evict_last: row re-read later
    ull pol;
    asm("createpolicy.fractional.L2::evict_last.b64 %0, 1.0;" : "=l"(pol));
    return pol;
}
__device__ __forceinline__ ull mk_stream() {   // evict_first: last use
    ull pol;
    asm("createpolicy.fractional.L2::evict_first.b64 %0, 1.0;" : "=l"(pol));
    return pol;
}
__device__ __forceinline__ ull ldg_pol(const float* p, ull pol) {
    ull v;
    asm volatile("ld.global.L2::cache_hint.b64 %0, [%1], %2;"
                 : "=l"(v) : "l"(p), "l"(pol));
    return v;
}
__device__ __forceinline__ void stg_pol(float* p, ull v, ull pol) {
    asm volatile("st.global.L2::cache_hint.b64 [%0], %1, %2;"
                 :: "l"(p), "l"(v), "l"(pol));
}
__device__ __forceinline__ void stg_cs(float* p, ull v) {
    asm volatile("st.global.cs.b64 [%0], %1;" :: "l"(p), "l"(v));
}

// ---------------------------------------------------------------------------
// One-time: liveness masks via reverse sweep over indices.
// mark[r]=1 iff row r is read by a module > m.
// ---------------------------------------------------------------------------
__global__ void alive_kernel(const int* __restrict__ indices) {
    __shared__ unsigned char mark[TOTAL];
    const int t = threadIdx.x;
    #pragma unroll
    for (int i = t; i < TOTAL; i += 1024) mark[i] = 0;
    __syncthreads();
    mark[indices[7 * 1024 + t]] = 1;          // reads of the last module
    __syncthreads();
    for (int m = DEPTH - 2; m >= 0; m--) {
        g_alive_sc[m][t] = mark[indices[m * 1024 + t]];
        if (t < 512) g_alive_act[m][t] = mark[IN_W + GROW * m + t];
        __syncthreads();
        if (m > 0) {
            mark[indices[m * 1024 + t]] = 1;
            __syncthreads();
        }
    }
}

// ---------------------------------------------------------------------------
// One butterfly module. CUDA block = (butterfly blk) x (256 batch cols).
// Thread owns 2 batch columns of all 16 rows as f32x2; transform in registers.
// occ-7 cap (72 regs) -> all 1024 CTAs resident in ONE wave, 28 warps/SM.
// PDL prologue computes trig via sincosf (overlapped with the predecessor);
// post-predecessor data (g_data / liveness masks) touched only after
// griddepsync. MODE: 0 = middle, 1 = first (input*scales), 2 = last (-> out)
// ---------------------------------------------------------------------------
template<int MODE>
__global__ __launch_bounds__(128, 7)
void module_kernel(const float* __restrict__ biases,  // [512]    this module
                   const int*   __restrict__ idx,     // [1024]   this module
                   const float* __restrict__ angles,  // [8][512] this module
                   int mod,
                   const float* __restrict__ input,   // (1024,4096) for FIRST
                   const float* __restrict__ scales,  // (1024,)     for FIRST
                   float* __restrict__ out_ext)       // d_out for LAST
{
    const int blk = blockIdx.y;
    const int tid = threadIdx.x;

    __shared__ int   s_idx[16];
    __shared__ ull   s_scl[16];
    __shared__ float s_bias[NACT];
    __shared__ unsigned char s_alsc[16];
    __shared__ unsigned char s_alact[NACT];
    __shared__ __align__(16) ulonglong2 s_cs[64];

    // ---- PDL prologue: trig + input-derived tables only.
    //      (MODE 1: liveness masks come from alive_kernel -> read post-sync)
    if (tid < 64) {
        int L = tid >> 3, a = tid & 7;
        float sn, cs;
        sincosf(angles[L * 512 + blk * 8 + a], &sn, &cs);
        s_cs[tid] = make_ulonglong2(pk2(cs, cs), pk2(sn, sn));
    }
    if (tid < 16) {
        int row = idx[blk * 16 + tid];
        s_idx[tid] = row;
        if (MODE != 1)
            s_alsc[tid] = (MODE == 2) ? 0 : g_alive_sc[mod][blk * 16 + tid];
        else { float s = scales[row]; s_scl[tid] = pk2(s, s); }
    }
    if (tid < 8) {
        s_bias[tid] = biases[blk * 8 + tid];
        if (MODE != 1)
            s_alact[tid] = (MODE == 2) ? 1 : g_alive_act[mod][blk * NACT + tid];
    }
    __syncthreads();

    const int b = (blockIdx.x * 128 + tid) * 2;   // first of 2 batch cols
    const ull SGN = 0x8000000080000000ULL;
    const ull pk  = mk_keep();
    const ull ps  = mk_stream();

    // ---- wait for previous kernel's stores (middle/last: g_data) ----
    if (MODE != 1) cudaGridDependencySynchronize();

    // Gather 16 rows (16 independent LDG.64 -> MLP=16). Last-use rows get
    // evict_first (they are also never scattered back).
    ull v[16];
    #pragma unroll
    for (int j = 0; j < 16; j++) {
        if (MODE == 1)
            v[j] = *(const ull*)(input + (size_t)s_idx[j] * BATCH + b);
        else
            v[j] = ldg_pol(g_data + (size_t)s_idx[j] * BATCH + b,
                           s_alsc[j] ? pk : ps);
    }
    if (MODE == 1) {
        #pragma unroll
        for (int j = 0; j < 16; j++) v[j] = mul2(v[j], s_scl[j]);
    }

    // 4 IN rotation layers (strides 1,2,4,8), all in registers
    #pragma unroll
    for (int k = 0; k < 4; k++) {
        const int st = 1 << k;
        #pragma unroll
        for (int g = 0; g < 16; g += 2 * st) {
            #pragma unroll
            for (int j = 0; j < st; j++) {
                const int lo = g + j, hi = lo + st;
                const ulonglong2 cs = s_cs[k * 8 + (g >> 1) + j];  // LDS.128
                const ull ns = cs.y ^ SGN;                         // -s on ALU
                ull xl = v[lo], xh = v[hi];
                v[lo] = fma2(cs.x, xl, mul2(cs.y, xh));
                v[hi] = fma2(ns,   xl, mul2(cs.x, xh));
            }
        }
    }

    // MODE 1: masks were produced by alive_kernel (our PDL predecessor) —
    // fetch them now, overlapped work done. Sync the CTA after staging.
    if (MODE == 1) {
        cudaGridDependencySynchronize();
        if (tid < 16) s_alsc[tid]  = g_alive_sc[0][blk * 16 + tid];
        if (tid < 8)  s_alact[tid] = g_alive_act[0][blk * NACT + tid];
        __syncthreads();
    }

    // Activation on rows 0..7; write live act rows (d_out for last module)
    #pragma unroll
    for (int u = 0; u < NACT; u++) {
        const float bb = s_bias[u];
        float x0, x1;
        upk2(v[u], x0, x1);
        x0 = actf(x0 + bb); x1 = actf(x1 + bb);
        v[u] = pk2(x0, x1);
        if (MODE == 2)
            stg_cs(out_ext + (size_t)(blk * NACT + u) * BATCH + b, v[u]);
        else if (s_alact[u])
            stg_pol(g_data + (size_t)(IN_W + GROW * mod + blk * NACT + u) * BATCH + b,
                    v[u], pk);
    }

    if (MODE != 2) {
        // 4 OUT rotation layers (trig layers 4..7, strides 1,2,4,8)
        #pragma unroll
        for (int k = 0; k < 4; k++) {
            const int st = 1 << k;
            #pragma unroll
            for (int g = 0; g < 16; g += 2 * st) {
                #pragma unroll
                for (int j = 0; j < st; j++) {
                    const int lo = g + j, hi = lo + st;
                    const ulonglong2 cs = s_cs[(4 + k) * 8 + (g >> 1) + j];
                    const ull ns = cs.y ^ SGN;
                    ull xl = v[lo], xh = v[hi];
                    v[lo] = fma2(cs.x, xl, mul2(cs.y, xh));
                    v[hi] = fma2(ns,   xl, mul2(cs.x, xh));
                }
            }
        }
        // Scatter back only live rows (warp-uniform predicate)
        #pragma unroll
        for (int j = 0; j < 16; j++)
            if (s_alsc[j])
                stg_pol(g_data + (size_t)s_idx[j] * BATCH + b, v[j], pk);
    }

    // Let the next PDL kernel in as soon as our work is done.
    cudaTriggerProgrammaticLaunchCompletion();
}

// ---------------------------------------------------------------------------
extern "C" void kernel_launch(void* const* d_in, const int* in_sizes, int n_in,
                              void* d_out, int out_size) {
    const float* input   = (const float*)d_in[0];   // (1024, 4096)
    const float* scales  = (const float*)d_in[1];   // (1024,)
    const float* angles  = (const float*)d_in[2];   // (8, 8, 512)
    const float* biases  = (const float*)d_in[3];   // (8, 512)
    const int*   indices = (const int*)d_in[4];     // (8, 1024)
    float* out = (float*)d_out;                     // (512, 4096)

    alive_kernel<<<1, 1024>>>(indices);

    dim3 grid(BATCH / (128 * 2), BLOCKS);   // (16, 64) = 1024 CTAs, one wave

    // All modules PDL-launched; module 0 overlaps with alive_kernel
    // (implicit completion trigger), modules 1..7 with the previous module.
    for (int m = 0; m < DEPTH; m++) {
        const float* bia = biases + (size_t)m * 512;
        const int*   ix  = indices + (size_t)m * 1024;
        const float* ang = angles + (size_t)m * 4096;

        cudaLaunchConfig_t cfg = {};
        cfg.gridDim  = grid;
        cfg.blockDim = dim3(128, 1, 1);
        cfg.dynamicSmemBytes = 0;
        cfg.stream = 0;
        cudaLaunchAttribute at[1];
        at[0].id = cudaLaunchAttributeProgrammaticStreamSerialization;
        at[0].val.programmaticStreamSerializationAllowed = 1;
        cfg.attrs = at;
        cfg.numAttrs = 1;

        if (m == 0)
            cudaLaunchKernelEx(&cfg, module_kernel<1>, bia, ix, ang, m,
                               input, scales, (float*)nullptr);
        else if (m < DEPTH - 1)
            cudaLaunchKernelEx(&cfg, module_kernel<0>, bia, ix, ang, m,
                               (const float*)nullptr, (const float*)nullptr,
                               (float*)nullptr);
        else
            cudaLaunchKernelEx(&cfg, module_kernel<2>, bia, ix, ang, m,
                               (const float*)nullptr, (const float*)nullptr,
                               out);
    }
}